// round 5
// baseline (speedup 1.0000x reference)
#include <cuda_runtime.h>
#include <cuda_fp16.h>
#include <math.h>
#include <stdint.h>

// Problem constants
#define B_  2
#define S_  2048
#define H_  1024
#define NH_ 16
#define HD_ 64
#define ROWS_ (B_ * S_)          // 4096

// Scratch (device globals: allocation-free)
__device__ __half g_Xh [ROWS_ * H_];     // hidden fp16
__device__ __half g_Wh [4 * H_ * H_];    // Wt q,k,v,o fp16 [n][k]
__device__ __half g_Qh [ROWS_ * H_];
__device__ __half g_Kh [ROWS_ * H_];
__device__ __half g_Vt [ROWS_ * H_];     // [(b*NH+h)*HD + d][S]
__device__ __half g_CTXh[ROWS_ * H_];
__device__ float  g_O  [ROWS_ * H_];

// ---------------------------------------------------------------------------
// PTX helpers
// ---------------------------------------------------------------------------
__device__ __forceinline__ uint32_t smem_u32(const void* p) {
    uint32_t a;
    asm("{ .reg .u64 t; cvta.to.shared.u64 t, %1; cvt.u32.u64 %0, t; }" : "=r"(a) : "l"(p));
    return a;
}
#define CP16(dst, src) \
    asm volatile("cp.async.cg.shared.global [%0], [%1], 16;" :: "r"(dst), "l"(src))
#define CP_COMMIT() asm volatile("cp.async.commit_group;" ::: "memory")
#define CP_WAIT0()  asm volatile("cp.async.wait_group 0;" ::: "memory")
#define CP_WAIT1()  asm volatile("cp.async.wait_group 1;" ::: "memory")

#define LDSM4(r, a) \
    asm volatile("ldmatrix.sync.aligned.m8n8.x4.shared.b16 {%0,%1,%2,%3}, [%4];" \
                 : "=r"((r)[0]), "=r"((r)[1]), "=r"((r)[2]), "=r"((r)[3]) : "r"(a))

#define MMA_F16(d, a, b0, b1) \
    asm volatile("mma.sync.aligned.m16n8k16.row.col.f32.f16.f16.f32 " \
                 "{%0,%1,%2,%3}, {%4,%5,%6,%7}, {%8,%9}, {%0,%1,%2,%3};" \
                 : "+f"((d)[0]), "+f"((d)[1]), "+f"((d)[2]), "+f"((d)[3]) \
                 : "r"((a)[0]), "r"((a)[1]), "r"((a)[2]), "r"((a)[3]), "r"(b0), "r"(b1))

__device__ __forceinline__ uint32_t f22h2(float a, float b) {
    __half2 h = __floats2half2_rn(a, b);
    return *(uint32_t*)&h;
}

// ---------------------------------------------------------------------------
// fp32 -> fp16 convert (vector of 8)
// ---------------------------------------------------------------------------
__global__ __launch_bounds__(256) void conv_h(
    const float* __restrict__ X, __half* __restrict__ Y, int n8)
{
    int i = blockIdx.x * blockDim.x + threadIdx.x;
    if (i >= n8) return;
    float4 a = *(const float4*)(X + i * 8);
    float4 b = *(const float4*)(X + i * 8 + 4);
    __half2 h[4];
    h[0] = __floats2half2_rn(a.x, a.y);
    h[1] = __floats2half2_rn(a.z, a.w);
    h[2] = __floats2half2_rn(b.x, b.y);
    h[3] = __floats2half2_rn(b.z, b.w);
    *(uint4*)(Y + i * 8) = *(uint4*)h;
}

// ---------------------------------------------------------------------------
// Transpose+convert all 4 weight matrices: W[K][N] fp32 -> Wt[z*H + n][k] fp16
// ---------------------------------------------------------------------------
__global__ __launch_bounds__(256) void convT(
    const float* __restrict__ W0, const float* __restrict__ W1,
    const float* __restrict__ W2, const float* __restrict__ W3,
    __half* __restrict__ T)
{
    __shared__ float t[32][33];
    const float* W = (blockIdx.z == 0) ? W0 : (blockIdx.z == 1) ? W1 :
                     (blockIdx.z == 2) ? W2 : W3;
    const int n0 = blockIdx.x * 32, k0 = blockIdx.y * 32;
    const int tx = threadIdx.x, ty = threadIdx.y;   // (32, 8)
#pragma unroll
    for (int r = 0; r < 32; r += 8)
        t[ty + r][tx] = W[(size_t)(k0 + ty + r) * H_ + n0 + tx];
    __syncthreads();
#pragma unroll
    for (int r = 0; r < 32; r += 8) {
        int n = n0 + ty + r, k = k0 + tx;
        T[((size_t)blockIdx.z * H_ + n) * H_ + k] = __float2half(t[tx][ty + r]);
    }
}

// ---------------------------------------------------------------------------
// fp16 GEMM mainloop: acc[2][8][4] += A[128,K] @ B[128,K]^T
// CTA 128x128, 8 warps (4m x 2n), K chunk 64, 3-stage cp.async pipeline.
// Smem tile row: 64 half = 128B + 16B pad = 144B (36 words ≡ 4 mod 32 ->
// conflict-free ldmatrix).
// ---------------------------------------------------------------------------
#define TILE_B  18432              // 128 * 144
#define STAGE_B (2 * TILE_B)       // 36864
#define GEMM_SMEM (3 * STAGE_B)    // 110592

__device__ __forceinline__ void gemm_mainloop(
    const __half* __restrict__ A, const __half* __restrict__ Bm,
    int rowBase, int colBase, char* smem, float acc[2][8][4])
{
    const int tid  = threadIdx.x;
    const int lane = tid & 31, wid = tid >> 5;
    const int wm   = wid >> 1, wn = wid & 1;
    const uint32_t smBase = smem_u32(smem);

    const int ld_row = tid >> 1;                 // 0..127
    const int ld_c0  = (tid & 1) * 4;            // 16B-chunk base: 0 or 4
    const size_t gA_off = (size_t)(rowBase + ld_row) * H_ + ld_c0 * 8;
    const size_t gB_off = (size_t)(colBase + ld_row) * H_ + ld_c0 * 8;
    const uint32_t st_off = ld_row * 144 + ld_c0 * 16;

    const int lrow = lane & 15;
    const int lhi  = (lane >> 4) * 16;
    uint32_t aoff[2], boff[4];
#pragma unroll
    for (int mt = 0; mt < 2; mt++) aoff[mt] = (wm * 32 + mt * 16 + lrow) * 144 + lhi;
#pragma unroll
    for (int g = 0; g < 4; g++)    boff[g]  = (wn * 64 + g * 16 + lrow) * 144 + lhi;

    const int KCH = H_ / 64;   // 16

#pragma unroll
    for (int s = 0; s < 2; s++) {
        const int kb = s * 64;
        uint32_t sb = smBase + s * STAGE_B + st_off;
        const __half* pa = A  + gA_off + kb;
        const __half* pb = Bm + gB_off + kb;
#pragma unroll
        for (int c = 0; c < 4; c++) {
            CP16(sb + c * 16,          pa + c * 8);
            CP16(sb + TILE_B + c * 16, pb + c * 8);
        }
        CP_COMMIT();
    }

    for (int cur = 0; cur < KCH; cur++) {
        CP_WAIT1();
        __syncthreads();

        const int nxt = cur + 2;
        if (nxt < KCH) {
            const int kb = nxt * 64;
            uint32_t sb = smBase + (nxt % 3) * STAGE_B + st_off;
            const __half* pa = A  + gA_off + kb;
            const __half* pb = Bm + gB_off + kb;
#pragma unroll
            for (int c = 0; c < 4; c++) {
                CP16(sb + c * 16,          pa + c * 8);
                CP16(sb + TILE_B + c * 16, pb + c * 8);
            }
        }
        CP_COMMIT();

        const uint32_t s0 = smBase + (cur % 3) * STAGE_B;
#pragma unroll
        for (int ks = 0; ks < 4; ks++) {
            const uint32_t ko = ks * 32;
            uint32_t Ah[2][4], Bh[4][4];
#pragma unroll
            for (int mt = 0; mt < 2; mt++) LDSM4(Ah[mt], s0 + aoff[mt] + ko);
#pragma unroll
            for (int g = 0; g < 4; g++)    LDSM4(Bh[g], s0 + TILE_B + boff[g] + ko);
#pragma unroll
            for (int mt = 0; mt < 2; mt++)
#pragma unroll
                for (int nt = 0; nt < 8; nt++) {
                    const int g = nt >> 1, ss = nt & 1;
                    MMA_F16(acc[mt][nt], Ah[mt], Bh[g][ss], Bh[g][ss + 2]);
                }
        }
    }
}

// ---------------------------------------------------------------------------
// Fused QKV GEMM: A=Xh [4096,1024], B=Wt[3072][1024]. Output per n-range:
//   n in [0,1024)    -> Qh fp16 [row][H]
//   n in [1024,2048) -> Kh fp16 [row][H]
//   n in [2048,3072) -> Vt fp16 transposed per head
// ---------------------------------------------------------------------------
__global__ __launch_bounds__(256) void gemm_qkv(
    const __half* __restrict__ A, const __half* __restrict__ Wt,
    const float* __restrict__ bq, const float* __restrict__ bk,
    const float* __restrict__ bv,
    __half* __restrict__ Qh, __half* __restrict__ Kh, __half* __restrict__ Vt)
{
    extern __shared__ char smem[];
    const int rowBase = blockIdx.y * 128;
    const int colBase = blockIdx.x * 128;   // 0..2944

    float acc[2][8][4];
#pragma unroll
    for (int i = 0; i < 2; i++)
#pragma unroll
        for (int j = 0; j < 8; j++)
#pragma unroll
            for (int k = 0; k < 4; k++) acc[i][j][k] = 0.f;

    gemm_mainloop(A, Wt, rowBase, colBase, smem, acc);

    const int lane = threadIdx.x & 31, wid = threadIdx.x >> 5;
    const int wm = wid >> 1, wn = wid & 1;
    const int erow = lane >> 2, ecol = (lane & 3) * 2;
    const int sel  = colBase >> 10;
    const int colM = colBase & 1023;
    const float* bias = (sel == 0) ? bq : (sel == 1) ? bk : bv;

#pragma unroll
    for (int mt = 0; mt < 2; mt++) {
        const int r0 = rowBase + wm * 32 + mt * 16 + erow;
#pragma unroll
        for (int nt = 0; nt < 8; nt++) {
            const int col = colM + wn * 64 + nt * 8 + ecol;
            const float b0 = bias[col], b1 = bias[col + 1];
            float v00 = acc[mt][nt][0] + b0, v01 = acc[mt][nt][1] + b1;
            float v10 = acc[mt][nt][2] + b0, v11 = acc[mt][nt][3] + b1;
            if (sel < 2) {
                __half* C = sel ? Kh : Qh;
                *(uint32_t*)&C[(size_t)r0 * H_ + col]       = f22h2(v00, v01);
                *(uint32_t*)&C[(size_t)(r0 + 8) * H_ + col] = f22h2(v10, v11);
            } else {
                const int h = col >> 6, d = col & 63;
                const int b_  = r0 >> 11;
                const int s0_ = r0 & 2047;
                size_t base0 = ((size_t)(b_ * NH_ + h) * HD_ + d) * S_;
                Vt[base0 + s0_]          = __float2half(v00);
                Vt[base0 + S_ + s0_]     = __float2half(v01);
                Vt[base0 + s0_ + 8]      = __float2half(v10);
                Vt[base0 + S_ + s0_ + 8] = __float2half(v11);
            }
        }
    }
}

// ---------------------------------------------------------------------------
// Output-proj GEMM: A=CTXh, B=Wt_o -> fp32 C + bias
// ---------------------------------------------------------------------------
__global__ __launch_bounds__(256) void gemm_out(
    const __half* __restrict__ A, const __half* __restrict__ Wt,
    const float* __restrict__ bias, float* __restrict__ C)
{
    extern __shared__ char smem[];
    const int rowBase = blockIdx.y * 128;
    const int colBase = blockIdx.x * 128;

    float acc[2][8][4];
#pragma unroll
    for (int i = 0; i < 2; i++)
#pragma unroll
        for (int j = 0; j < 8; j++)
#pragma unroll
            for (int k = 0; k < 4; k++) acc[i][j][k] = 0.f;

    gemm_mainloop(A, Wt, rowBase, colBase, smem, acc);

    const int lane = threadIdx.x & 31, wid = threadIdx.x >> 5;
    const int wm = wid >> 1, wn = wid & 1;
    const int erow = lane >> 2, ecol = (lane & 3) * 2;

#pragma unroll
    for (int mt = 0; mt < 2; mt++) {
        const int r0 = rowBase + wm * 32 + mt * 16 + erow;
#pragma unroll
        for (int nt = 0; nt < 8; nt++) {
            const int col = colBase + wn * 64 + nt * 8 + ecol;
            const float b0 = bias[col], b1 = bias[col + 1];
            float2 v0, v1;
            v0.x = acc[mt][nt][0] + b0; v0.y = acc[mt][nt][1] + b1;
            v1.x = acc[mt][nt][2] + b0; v1.y = acc[mt][nt][3] + b1;
            *(float2*)&C[(size_t)r0 * H_ + col]       = v0;
            *(float2*)&C[(size_t)(r0 + 8) * H_ + col] = v1;
        }
    }
}

// ---------------------------------------------------------------------------
// fp16 tensor-core flash attention, 8 warps / 256 threads.
// CTA: 128 queries x one (b,h). Warp = 16 query rows (no mt loop).
// K/V tiles of 64 keys double-buffered via cp.async. V pre-transposed [d][s].
// Smem rows padded to 144B -> conflict-free ldmatrix.
// ---------------------------------------------------------------------------
#define AQ_OFF 0                       // Q: 128*144 = 18432
#define AK_OFF 18432                   // K: 2 * 64*144 = 18432
#define AV_OFF (18432 + 18432)         // V: 2 * 9216
#define AM_OFF (18432 + 2 * 18432)     // mask: 2 * 256B
#define ATTN_SMEM (AM_OFF + 512)

__global__ __launch_bounds__(256) void attn_f16(
    const __half* __restrict__ Qh, const __half* __restrict__ Kh,
    const __half* __restrict__ Vt, const float* __restrict__ mask,
    __half* __restrict__ CTXh)
{
    extern __shared__ char smem[];
    const int tid = threadIdx.x, lane = tid & 31, wid = tid >> 5;
    const int qb = blockIdx.x * 128, h = blockIdx.y, b = blockIdx.z;
    const uint32_t sm = smem_u32(smem);

    const __half* Qg = Qh + ((size_t)(b * S_ + qb)) * H_ + h * HD_;
    const __half* Kg = Kh + ((size_t)(b * S_)) * H_ + h * HD_;
    const __half* Vg = Vt + ((size_t)((b * NH_ + h) * HD_)) * S_;
    const float*  Mg = mask + b * S_;

    // ---- prologue: Q tile + K/V/mask tile 0 ----
    {
        const int r = tid >> 1, c0 = (tid & 1) * 4;
        const char* src = (const char*)(Qg + (size_t)r * H_) + c0 * 16;
        uint32_t dst = sm + AQ_OFF + r * 144 + c0 * 16;
#pragma unroll
        for (int c = 0; c < 4; c++) CP16(dst + c * 16, src + c * 16);
    }
    {
        const int r = tid >> 2, c0 = (tid & 3) * 2;
        const char* ks = (const char*)(Kg + (size_t)r * H_) + c0 * 16;
        const char* vs = (const char*)(Vg + (size_t)r * S_) + c0 * 16;
        uint32_t kd = sm + AK_OFF + r * 144 + c0 * 16;
        uint32_t vd = sm + AV_OFF + r * 144 + c0 * 16;
        CP16(kd,      ks);      CP16(kd + 16, ks + 16);
        CP16(vd,      vs);      CP16(vd + 16, vs + 16);
    }
    if (tid < 16) CP16(sm + AM_OFF + tid * 16, (const char*)Mg + tid * 16);
    CP_COMMIT();
    CP_WAIT0();
    __syncthreads();

    // ---- Q fragments (16 rows per warp, held all kernel) ----
    const int lrow = lane & 15;
    const int lhi  = (lane >> 4) * 16;
    uint32_t Qf[4][4];
#pragma unroll
    for (int kk = 0; kk < 4; kk++)
        LDSM4(Qf[kk], sm + AQ_OFF + (wid * 16 + lrow) * 144 + kk * 32 + lhi);

    float O[8][4];
#pragma unroll
    for (int j = 0; j < 8; j++)
#pragma unroll
        for (int k = 0; k < 4; k++) O[j][k] = 0.f;
    float m0 = -1e30f, m1 = -1e30f, l0 = 0.f, l1 = 0.f;

    const int c0q = (lane & 3) * 2;
    const int NKT = S_ / 64;   // 32
    for (int kt = 0; kt < NKT; kt++) {
        const int buf = kt & 1;

        // issue next tile into buf^1
        if (kt + 1 < NKT) {
            const int k0n = (kt + 1) * 64;
            const int nb = buf ^ 1;
            const int r = tid >> 2, cc = (tid & 3) * 2;
            const char* ks = (const char*)(Kg + (size_t)(k0n + r) * H_) + cc * 16;
            const char* vs = (const char*)(Vg + (size_t)r * S_ + k0n) + cc * 16;
            uint32_t kd = sm + AK_OFF + nb * 9216 + r * 144 + cc * 16;
            uint32_t vd = sm + AV_OFF + nb * 9216 + r * 144 + cc * 16;
            CP16(kd,      ks);      CP16(kd + 16, ks + 16);
            CP16(vd,      vs);      CP16(vd + 16, vs + 16);
            if (tid < 16)
                CP16(sm + AM_OFF + nb * 256 + tid * 16,
                     (const char*)(Mg + k0n) + tid * 16);
        }
        CP_COMMIT();
        CP_WAIT1();
        __syncthreads();

        const uint32_t skb = sm + AK_OFF + buf * 9216;
        const uint32_t svb = sm + AV_OFF + buf * 9216;
        const float* mk = (const float*)(smem + AM_OFF + buf * 256);

        float Sf[8][4];
#pragma unroll
        for (int j = 0; j < 8; j++)
#pragma unroll
            for (int k = 0; k < 4; k++) Sf[j][k] = 0.f;

        // S = Q K^T
#pragma unroll
        for (int g = 0; g < 4; g++) {
            uint32_t KB[4][4];
#pragma unroll
            for (int kk = 0; kk < 4; kk++)
                LDSM4(KB[kk], skb + (g * 16 + lrow) * 144 + kk * 32 + lhi);
#pragma unroll
            for (int ss = 0; ss < 2; ss++) {
                const int nt = g * 2 + ss;
#pragma unroll
                for (int kk = 0; kk < 4; kk++)
                    MMA_F16(Sf[nt], Qf[kk], KB[kk][ss], KB[kk][ss + 2]);
            }
        }

        // scale + mask + online softmax (conditional rescale)
        float x0 = -1e30f, x1 = -1e30f;
#pragma unroll
        for (int j = 0; j < 8; j++) {
            const float mm0 = mk[j * 8 + c0q], mm1 = mk[j * 8 + c0q + 1];
            Sf[j][0] = Sf[j][0] * 0.125f + mm0;
            Sf[j][1] = Sf[j][1] * 0.125f + mm1;
            Sf[j][2] = Sf[j][2] * 0.125f + mm0;
            Sf[j][3] = Sf[j][3] * 0.125f + mm1;
            x0 = fmaxf(x0, fmaxf(Sf[j][0], Sf[j][1]));
            x1 = fmaxf(x1, fmaxf(Sf[j][2], Sf[j][3]));
        }
        x0 = fmaxf(x0, __shfl_xor_sync(0xffffffffu, x0, 1));
        x0 = fmaxf(x0, __shfl_xor_sync(0xffffffffu, x0, 2));
        x1 = fmaxf(x1, __shfl_xor_sync(0xffffffffu, x1, 1));
        x1 = fmaxf(x1, __shfl_xor_sync(0xffffffffu, x1, 2));

        if (x0 > m0) {
            const float cor = __expf(m0 - x0);
            l0 *= cor;
#pragma unroll
            for (int j = 0; j < 8; j++) { O[j][0] *= cor; O[j][1] *= cor; }
            m0 = x0;
        }
        if (x1 > m1) {
            const float cor = __expf(m1 - x1);
            l1 *= cor;
#pragma unroll
            for (int j = 0; j < 8; j++) { O[j][2] *= cor; O[j][3] *= cor; }
            m1 = x1;
        }

        float rs0 = 0.f, rs1 = 0.f;
#pragma unroll
        for (int j = 0; j < 8; j++) {
            Sf[j][0] = __expf(Sf[j][0] - m0);
            Sf[j][1] = __expf(Sf[j][1] - m0);
            Sf[j][2] = __expf(Sf[j][2] - m1);
            Sf[j][3] = __expf(Sf[j][3] - m1);
            rs0 += Sf[j][0] + Sf[j][1];
            rs1 += Sf[j][2] + Sf[j][3];
        }
        rs0 += __shfl_xor_sync(0xffffffffu, rs0, 1);
        rs0 += __shfl_xor_sync(0xffffffffu, rs0, 2);
        rs1 += __shfl_xor_sync(0xffffffffu, rs1, 1);
        rs1 += __shfl_xor_sync(0xffffffffu, rs1, 2);
        l0 += rs0;
        l1 += rs1;

        // P fragments (A-frag layout from S accumulator layout)
        uint32_t P[4][4];
#pragma unroll
        for (int t = 0; t < 4; t++) {
            P[t][0] = f22h2(Sf[2 * t][0],     Sf[2 * t][1]);
            P[t][1] = f22h2(Sf[2 * t][2],     Sf[2 * t][3]);
            P[t][2] = f22h2(Sf[2 * t + 1][0], Sf[2 * t + 1][1]);
            P[t][3] = f22h2(Sf[2 * t + 1][2], Sf[2 * t + 1][3]);
        }

        // O += P @ V  (V as [d][key], B frags via plain ldmatrix)
#pragma unroll
        for (int g = 0; g < 4; g++) {
            uint32_t VB[4][4];
#pragma unroll
            for (int t = 0; t < 4; t++)
                LDSM4(VB[t], svb + (g * 16 + lrow) * 144 + t * 32 + lhi);
#pragma unroll
            for (int ss = 0; ss < 2; ss++) {
                const int nt = g * 2 + ss;
#pragma unroll
                for (int t = 0; t < 4; t++)
                    MMA_F16(O[nt], P[t], VB[t][ss], VB[t][ss + 2]);
            }
        }
        __syncthreads();
    }

    // ---- epilogue: normalize, store CTX fp16 ----
    const int erow = lane >> 2, ecol = (lane & 3) * 2;
    const float i0 = 1.f / l0;
    const float i1 = 1.f / l1;
    const int r0 = qb + wid * 16 + erow;
#pragma unroll
    for (int j = 0; j < 8; j++) {
        const int col = h * HD_ + j * 8 + ecol;
        *(uint32_t*)&CTXh[(size_t)(b * S_ + r0) * H_ + col] =
            f22h2(O[j][0] * i0, O[j][1] * i0);
        *(uint32_t*)&CTXh[(size_t)(b * S_ + r0 + 8) * H_ + col] =
            f22h2(O[j][2] * i1, O[j][3] * i1);
    }
}

// ---------------------------------------------------------------------------
// Residual add + LayerNorm (eps 1e-12).
// ---------------------------------------------------------------------------
__device__ __forceinline__ float warp_sum(float v) {
#pragma unroll
    for (int o = 16; o > 0; o >>= 1) v += __shfl_xor_sync(0xffffffffu, v, o);
    return v;
}

__global__ __launch_bounds__(256) void resid_ln(
    const float* __restrict__ X, const float* __restrict__ R,
    const float* __restrict__ gamma, const float* __restrict__ beta,
    float* __restrict__ out)
{
    const int row = blockIdx.x;
    const int t = threadIdx.x;
    const float* x = X + (size_t)row * H_;
    const float* r = R + (size_t)row * H_;

    float4 xv = *(const float4*)(x + t * 4);
    float4 rv = *(const float4*)(r + t * 4);
    float v[4] = { xv.x + rv.x, xv.y + rv.y, xv.z + rv.z, xv.w + rv.w };

    float s = v[0] + v[1] + v[2] + v[3];
    float s2 = v[0] * v[0] + v[1] * v[1] + v[2] * v[2] + v[3] * v[3];

    __shared__ float red1[8], red2[8];
    float ws = warp_sum(s), ws2 = warp_sum(s2);
    int wid = t >> 5, lid = t & 31;
    if (lid == 0) { red1[wid] = ws; red2[wid] = ws2; }
    __syncthreads();
    if (wid == 0) {
        float a = (lid < 8) ? red1[lid] : 0.f;
        float b2 = (lid < 8) ? red2[lid] : 0.f;
        a = warp_sum(a); b2 = warp_sum(b2);
        if (lid == 0) { red1[0] = a; red2[0] = b2; }
    }
    __syncthreads();

    float mean = red1[0] * (1.f / H_);
    float var = red2[0] * (1.f / H_) - mean * mean;
    float rstd = rsqrtf(var + 1e-12f);

    float4 g4 = *(const float4*)(gamma + t * 4);
    float4 b4 = *(const float4*)(beta + t * 4);
    float4 o;
    o.x = (v[0] - mean) * rstd * g4.x + b4.x;
    o.y = (v[1] - mean) * rstd * g4.y + b4.y;
    o.z = (v[2] - mean) * rstd * g4.z + b4.z;
    o.w = (v[3] - mean) * rstd * g4.w + b4.w;
    *(float4*)(out + (size_t)row * H_ + t * 4) = o;
}

// ---------------------------------------------------------------------------
// Launch
// ---------------------------------------------------------------------------
extern "C" void kernel_launch(void* const* d_in, const int* in_sizes, int n_in,
                              void* d_out, int out_size)
{
    const float* hidden = (const float*)d_in[0];
    const float* mask   = (const float*)d_in[1];
    const float* Wq = (const float*)d_in[2];
    const float* bq = (const float*)d_in[3];
    const float* Wk = (const float*)d_in[4];
    const float* bk = (const float*)d_in[5];
    const float* Wv = (const float*)d_in[6];
    const float* bv = (const float*)d_in[7];
    const float* Wo = (const float*)d_in[8];
    const float* bo = (const float*)d_in[9];
    const float* gamma = (const float*)d_in[10];
    const float* beta  = (const float*)d_in[11];
    float* out = (float*)d_out;

    __half *Xh, *Wh, *Qh, *Kh, *Vt, *CTXh;
    float* O;
    cudaGetSymbolAddress((void**)&Xh,   g_Xh);
    cudaGetSymbolAddress((void**)&Wh,   g_Wh);
    cudaGetSymbolAddress((void**)&Qh,   g_Qh);
    cudaGetSymbolAddress((void**)&Kh,   g_Kh);
    cudaGetSymbolAddress((void**)&Vt,   g_Vt);
    cudaGetSymbolAddress((void**)&CTXh, g_CTXh);
    cudaGetSymbolAddress((void**)&O,    g_O);

    static bool attr_set = false;
    if (!attr_set) {
        cudaFuncSetAttribute(gemm_qkv, cudaFuncAttributeMaxDynamicSharedMemorySize, GEMM_SMEM);
        cudaFuncSetAttribute(gemm_out, cudaFuncAttributeMaxDynamicSharedMemorySize, GEMM_SMEM);
        cudaFuncSetAttribute(attn_f16, cudaFuncAttributeMaxDynamicSharedMemorySize, ATTN_SMEM);
        attr_set = true;
    }

    const int n8 = ROWS_ * H_ / 8;
    conv_h<<<(n8 + 255) / 256, 256>>>(hidden, Xh, n8);

    dim3 tgrid(H_ / 32, H_ / 32, 4);
    convT<<<tgrid, dim3(32, 8)>>>(Wq, Wk, Wv, Wo, Wh);

    dim3 qkvgrid(3 * H_ / 128, ROWS_ / 128);   // (24, 32)
    gemm_qkv<<<qkvgrid, 256, GEMM_SMEM>>>(Xh, Wh, bq, bk, bv, Qh, Kh, Vt);

    dim3 agrid(S_ / 128, NH_, B_);             // (16, 16, 2)
    attn_f16<<<agrid, 256, ATTN_SMEM>>>(Qh, Kh, Vt, mask, CTXh);

    dim3 ogrid(H_ / 128, ROWS_ / 128);         // (8, 32)
    gemm_out<<<ogrid, 256, GEMM_SMEM>>>(CTXh, Wh + 3 * (size_t)H_ * H_, bo, O);

    resid_ln<<<ROWS_, 256>>>(O, hidden, gamma, beta, out);
}